// round 10
// baseline (speedup 1.0000x reference)
#include <cuda_runtime.h>
#include <cuda_fp16.h>
#include <cstdint>

// ============================================================================
// Problem constants
// ============================================================================
#define M_TOTAL 8192   // B*S = 4*2048
#define DIN     2048
#define DOUT    2048
#define QDIV    358.4f // 448 * 0.8

// GEMM tiling (f16 carrier): 128x128 CTA tile, BK=64, 3 stages, 256 threads,
// 2 CTAs per SM. Split-K=2: each CTA does half of K; producer/consumer
// combine via flags (kills the 4T->3.5T tail quantization).
#define BM 128
#define BN 128
#define BK 64
#define STAGES 3
#define KHALF  (DIN / 2)     // 1024
#define NIT    (KHALF / BK)  // 16
#define NTILES ((M_TOTAL / BM) * (DOUT / BN))  // 1024

#define AMAX_XBLK 1024
#define AMAX_WBLK 512
#define QUANT_XBLK 4096
#define QUANT_WBLK 1024

// ============================================================================
// Device-global scratch (allocation-free requirement)
// ============================================================================
__device__ float g_px[AMAX_XBLK];   // per-block |x| maxes (plain stores)
__device__ float g_pw[AMAX_WBLK];   // per-block |w| maxes
__device__ float g_osc;             // sx*sw, published by quant block 0
__device__ unsigned g_flag[NTILES]; // split-K producer-done flags
__device__ __align__(128) float g_part[(size_t)M_TOTAL * DOUT];  // 64 MB
// fp8-rounded values stored as f16 (exact: e4m3 subset of f16)
__device__ __align__(128) __half g_qx[(size_t)M_TOTAL * DIN];   // 32 MB
__device__ __align__(128) __half g_qw[(size_t)DOUT * DIN];      //  8 MB

// ============================================================================
// Helpers
// ============================================================================
__device__ __forceinline__ uint32_t smem_to_u32(const void* p) {
    uint32_t a;
    asm("{ .reg .u64 t; cvta.to.shared.u64 t, %1; cvt.u32.u64 %0, t; }"
        : "=r"(a) : "l"(p));
    return a;
}

// fp32x2 -> packed e4m3x2 (RN, satfinite). low byte = lo, high byte = hi.
__device__ __forceinline__ uint16_t cvt_e4m3x2(float hi, float lo) {
    uint16_t r;
    asm("cvt.rn.satfinite.e4m3x2.f32 %0, %1, %2;" : "=h"(r) : "f"(hi), "f"(lo));
    return r;
}

// packed e4m3x2 -> f16x2 (exact)
__device__ __forceinline__ uint32_t cvt_f16x2_from_e4m3x2(uint16_t e) {
    uint32_t r;
    asm("cvt.rn.f16x2.e4m3x2 %0, %1;" : "=r"(r) : "h"(e));
    return r;
}

#define CP_ASYNC_16(dst, src) \
    asm volatile("cp.async.cg.shared.global [%0], [%1], 16;" \
                 :: "r"(dst), "l"(src))
#define CP_ASYNC_COMMIT() asm volatile("cp.async.commit_group;")
#define CP_ASYNC_WAIT_1() asm volatile("cp.async.wait_group 1;")

#define LDSM_X4(r, addr) \
    asm volatile("ldmatrix.sync.aligned.m8n8.x4.shared.b16 {%0,%1,%2,%3}, [%4];" \
        : "=r"((r)[0]), "=r"((r)[1]), "=r"((r)[2]), "=r"((r)[3]) : "r"(addr))

__device__ __forceinline__ void mma16816(float* d, const uint32_t* a,
                                         const uint32_t* b) {
    asm volatile(
        "mma.sync.aligned.m16n8k16.row.col.f32.f16.f16.f32 "
        "{%0,%1,%2,%3}, {%4,%5,%6,%7}, {%8,%9}, {%0,%1,%2,%3};"
        : "+f"(d[0]), "+f"(d[1]), "+f"(d[2]), "+f"(d[3])
        : "r"(a[0]), "r"(a[1]), "r"(a[2]), "r"(a[3]), "r"(b[0]), "r"(b[1]));
}

// SW128 swizzle for 128-byte rows (byte offsets)
__device__ __forceinline__ uint32_t swz(uint32_t off) {
    return off ^ ((off >> 3) & 0x70);
}

// div via reciprocal + one FMA residual refinement (== IEEE div for all but
// ~2^-40 of inputs; 3-mantissa-bit e4m3 RNE absorbs the rest)
__device__ __forceinline__ float div_cr(float x, float s, float inv) {
    float y = x * inv;
    float e = fmaf(-s, y, x);
    return fmaf(e, inv, y);
}

__device__ __forceinline__ float max4(float4 v) {
    return fmaxf(fmaxf(fabsf(v.x), fabsf(v.y)),
                 fmaxf(fabsf(v.z), fabsf(v.w)));
}

// block-level max reduction (256 threads), result valid in thread 0
__device__ __forceinline__ float block_max_256(float m, float* sred) {
    #pragma unroll
    for (int o = 16; o; o >>= 1)
        m = fmaxf(m, __shfl_xor_sync(0xFFFFFFFFu, m, o));
    if ((threadIdx.x & 31) == 0) sred[threadIdx.x >> 5] = m;
    __syncthreads();
    if (threadIdx.x < 8) {
        m = sred[threadIdx.x];
        #pragma unroll
        for (int o = 4; o; o >>= 1)
            m = fmaxf(m, __shfl_xor_sync(0xFFu, m, o));
    }
    return m;
}

// ============================================================================
// Kernel 1: fused amax over x (blocks [0,1024)) and w (blocks [1024,1536)).
// ============================================================================
__global__ void amax_kernel(const float4* __restrict__ x,
                            const float4* __restrict__ w) {
    __shared__ float sred[8];
    const bool is_w = blockIdx.x >= AMAX_XBLK;
    const float4* p = is_w ? w : x;
    const int n4 = is_w ? (DOUT * DIN / 4) : (M_TOTAL * DIN / 4);
    const int nblk = is_w ? AMAX_WBLK : AMAX_XBLK;
    const int b0 = is_w ? AMAX_XBLK : 0;
    const int bid = blockIdx.x - b0;
    const int stride = nblk * 256 * 4;
    float m0 = 0.0f, m1 = 0.0f, m2 = 0.0f, m3 = 0.0f;
    for (int i = bid * 256 * 4 + threadIdx.x; i < n4; i += stride) {
        float4 v0 = p[i];
        float4 v1 = p[i + 256];
        float4 v2 = p[i + 512];
        float4 v3 = p[i + 768];
        m0 = fmaxf(m0, max4(v0));
        m1 = fmaxf(m1, max4(v1));
        m2 = fmaxf(m2, max4(v2));
        m3 = fmaxf(m3, max4(v3));
    }
    float m = fmaxf(fmaxf(m0, m1), fmaxf(m2, m3));
    m = block_max_256(m, sred);
    if (threadIdx.x == 0) {
        if (is_w) g_pw[bid] = m;
        else      g_px[bid] = m;
    }
}

// ============================================================================
// Kernel 2: fused quantize x/w + split-K flag reset (blocks 0..3).
// Block 0 publishes g_osc.
// ============================================================================
__global__ void quant_kernel(const float4* __restrict__ x,
                             const float4* __restrict__ w) {
    __shared__ float sred[8];
    __shared__ float s_ax, s_aw;
    // reset split-K flags for the upcoming gemm (stream-ordered before it)
    if (blockIdx.x < 4)
        g_flag[(blockIdx.x << 8) | threadIdx.x] = 0u;
    {
        float mx = 0.0f, mw = 0.0f;
        #pragma unroll
        for (int q = 0; q < 4; ++q)
            mx = fmaxf(mx, g_px[threadIdx.x + q * 256]);
        #pragma unroll
        for (int q = 0; q < 2; ++q)
            mw = fmaxf(mw, g_pw[threadIdx.x + q * 256]);
        float rx = block_max_256(mx, sred);
        if (threadIdx.x == 0) s_ax = rx;
        __syncthreads();
        float rw = block_max_256(mw, sred);
        if (threadIdx.x == 0) s_aw = rw;
        __syncthreads();
    }
    const float ax = s_ax, aw = s_aw;
    if (blockIdx.x == 0 && threadIdx.x == 0)
        g_osc = (ax / QDIV) * (fmaxf(ax, aw) / QDIV);

    const bool is_w = blockIdx.x >= QUANT_XBLK;
    const float s   = is_w ? (fmaxf(ax, aw) / QDIV) : (ax / QDIV);
    const float inv = 1.0f / s;
    const float4* p = is_w ? w : x;
    uint4* q = (uint4*)(is_w ? (void*)g_qw : (void*)g_qx);
    const int n8 = (is_w ? (DOUT * DIN) : (M_TOTAL * DIN)) / 8;
    const int nblk = is_w ? QUANT_WBLK : QUANT_XBLK;
    const int b0 = is_w ? QUANT_XBLK : 0;
    for (int i = (blockIdx.x - b0) * 256 + threadIdx.x; i < n8;
         i += nblk * 256) {
        float4 v0 = p[2 * i];
        float4 v1 = p[2 * i + 1];
        uint4 o;
        o.x = cvt_f16x2_from_e4m3x2(cvt_e4m3x2(div_cr(v0.y, s, inv),
                                               div_cr(v0.x, s, inv)));
        o.y = cvt_f16x2_from_e4m3x2(cvt_e4m3x2(div_cr(v0.w, s, inv),
                                               div_cr(v0.z, s, inv)));
        o.z = cvt_f16x2_from_e4m3x2(cvt_e4m3x2(div_cr(v1.y, s, inv),
                                               div_cr(v1.x, s, inv)));
        o.w = cvt_f16x2_from_e4m3x2(cvt_e4m3x2(div_cr(v1.w, s, inv),
                                               div_cr(v1.z, s, inv)));
        q[i] = o;
    }
}

// ============================================================================
// Kernel 3: f16 HMMA GEMM, split-K=2.
// z=0 CTAs (dispatched first): k in [0,1024) -> raw partials + flag.
// z=1 CTAs: k in [1024,2048) -> spin on flag, combine, scale+bias, store.
// Deterministic: fixed combine order, no data atomics.
// ============================================================================
#define STAGE_BYTES 32768                 // A 16KB + B 16KB
#define GEMM_SMEM_BYTES (STAGES * STAGE_BYTES)   // 98304

__global__ __launch_bounds__(256, 2) void gemm_kernel(
    float* __restrict__ out, const float* __restrict__ bias)
{
    extern __shared__ char smem[];
    const uint32_t sb = smem_to_u32(smem);
    const int tid  = threadIdx.x;
    const int lane = tid & 31;
    const int warp = tid >> 5;
    const int wm = warp >> 2;       // 0..1
    const int wn = warp & 3;        // 0..3
    const int nt = blockIdx.x;      // 0..15
    const int mt = blockIdx.y;      // 0..63
    const int kt = blockIdx.z;      // 0..1 (split-K half)
    const int tile = mt * (DOUT / BN) + nt;   // 0..1023

    const __half* gA = g_qx + (size_t)mt * BM * DIN + (size_t)kt * KHALF;
    const __half* gB = g_qw + (size_t)nt * BN * DIN + (size_t)kt * KHALF;

    // ---- bias prefetch ----
    const int n0 = nt * BN + wn * 32 + (lane & 3) * 2;
    float biasr[8];
    #pragma unroll
    for (int j = 0; j < 4; ++j) {
        biasr[2 * j]     = __ldg(&bias[n0 + j * 8]);
        biasr[2 * j + 1] = __ldg(&bias[n0 + j * 8 + 1]);
    }

    // ---- per-thread cp.async chunk map: 4 chunks A + 4 chunks B per stage ----
    uint32_t dstA[4], dstB[4];
    const char* srcA[4];
    const char* srcB[4];
    #pragma unroll
    for (int q = 0; q < 4; ++q) {
        int ch  = tid + q * 256;
        int row = ch >> 3;
        int cb  = (ch & 7) * 16;
        uint32_t sw = swz((uint32_t)(row * 128 + cb));
        dstA[q] = sw;
        dstB[q] = 16384u + sw;
        srcA[q] = (const char*)(gA + (size_t)row * DIN) + cb;
        srcB[q] = (const char*)(gB + (size_t)row * DIN) + cb;
    }

    // ---- prologue: fill STAGES-1 stages ----
    int li = 0;
    #pragma unroll
    for (int s = 0; s < STAGES - 1; ++s) {
        uint32_t st = sb + s * STAGE_BYTES;
        #pragma unroll
        for (int q = 0; q < 4; ++q) {
            CP_ASYNC_16(st + dstA[q], srcA[q] + li * (BK * 2));
            CP_ASYNC_16(st + dstB[q], srcB[q] + li * (BK * 2));
        }
        CP_ASYNC_COMMIT();
        ++li;
    }
    CP_ASYNC_WAIT_1();
    __syncthreads();

    // ---- ldmatrix per-lane address components ----
    const int rA = wm * 64 + (lane & 7) + ((lane >> 3) & 1) * 8;
    const uint32_t cA0 = ((lane >> 4) & 1) * 16;
    const uint32_t xrA = (uint32_t)((rA & 7) << 4);
    const int rB = wn * 32 + (lane & 7) + ((lane >> 4) & 1) * 8;
    const uint32_t cB0 = ((lane >> 3) & 1) * 16;
    const uint32_t xrB = (uint32_t)((rB & 7) << 4);

    float acc[4][4][4];
    #pragma unroll
    for (int i = 0; i < 4; ++i)
        #pragma unroll
        for (int j = 0; j < 4; ++j)
            #pragma unroll
            for (int r = 0; r < 4; ++r) acc[i][j][r] = 0.0f;

    // double-buffered fragments
    uint32_t afr[2][4][4];
    uint32_t bfr[2][2][4];

    // ---- main loop (NIT = 16 over this CTA's K half) ----
    #pragma unroll 1
    for (int it = 0; it < NIT; ++it) {
        const int cur = it % STAGES;
        const uint32_t stA = sb + cur * STAGE_BYTES;
        const uint32_t stB = stA + 16384;

        // k0 fragment preload (stage cur complete & synced)
        #pragma unroll
        for (int i = 0; i < 4; ++i)
            LDSM_X4(afr[0][i], stA + (uint32_t)((rA + i * 16) * 128) + (cA0 ^ xrA));
        #pragma unroll
        for (int jj = 0; jj < 2; ++jj)
            LDSM_X4(bfr[0][jj], stB + (uint32_t)((rB + jj * 16) * 128) + (cB0 ^ xrB));

        if (li < NIT) {
            const int nx = (it + STAGES - 1) % STAGES;
            uint32_t st = sb + nx * STAGE_BYTES;
            #pragma unroll
            for (int q = 0; q < 4; ++q) {
                CP_ASYNC_16(st + dstA[q], srcA[q] + li * (BK * 2));
                CP_ASYNC_16(st + dstB[q], srcB[q] + li * (BK * 2));
            }
            ++li;
        }
        CP_ASYNC_COMMIT();

        #pragma unroll
        for (int s = 0; s < 4; ++s) {
            const int cb = s & 1, nb = cb ^ 1;
            if (s < 3) {
                #pragma unroll
                for (int i = 0; i < 4; ++i)
                    LDSM_X4(afr[nb][i], stA + (uint32_t)((rA + i * 16) * 128)
                                            + ((cA0 + (s + 1) * 32) ^ xrA));
                #pragma unroll
                for (int jj = 0; jj < 2; ++jj)
                    LDSM_X4(bfr[nb][jj], stB + (uint32_t)((rB + jj * 16) * 128)
                                             + ((cB0 + (s + 1) * 32) ^ xrB));
            }
            #pragma unroll
            for (int i = 0; i < 4; ++i)
                #pragma unroll
                for (int j = 0; j < 4; ++j)
                    mma16816(acc[i][j], afr[cb][i], bfr[cb][j >> 1] + (j & 1) * 2);
        }

        CP_ASYNC_WAIT_1();
        __syncthreads();
    }

    const int m0 = mt * BM + wm * 64 + (lane >> 2);

    if (kt == 0) {
        // ---- producer: raw partials to scratch, then flag ----
        #pragma unroll
        for (int i = 0; i < 4; ++i) {
            #pragma unroll
            for (int j = 0; j < 4; ++j) {
                const int m = m0 + i * 16;
                const int n = n0 + j * 8;
                float2 v0, v1;
                v0.x = acc[i][j][0]; v0.y = acc[i][j][1];
                v1.x = acc[i][j][2]; v1.y = acc[i][j][3];
                *(float2*)&g_part[(size_t)m * DOUT + n]       = v0;
                *(float2*)&g_part[(size_t)(m + 8) * DOUT + n] = v1;
            }
        }
        __threadfence();
        __syncthreads();
        if (tid == 0) atomicExch(&g_flag[tile], 1u);
    } else {
        // ---- consumer: wait for producer, combine, scale + bias, store ----
        if (tid == 0) {
            while (atomicAdd(&g_flag[tile], 0u) == 0u) __nanosleep(64);
        }
        __syncthreads();
        const float osc = g_osc;
        #pragma unroll
        for (int i = 0; i < 4; ++i) {
            #pragma unroll
            for (int j = 0; j < 4; ++j) {
                const int m = m0 + i * 16;
                const int n = n0 + j * 8;
                // L2-coherent reads (bypass L1; producer stores are in L2)
                float2 p0 = __ldcg((const float2*)&g_part[(size_t)m * DOUT + n]);
                float2 p1 = __ldcg((const float2*)&g_part[(size_t)(m + 8) * DOUT + n]);
                float2 v0, v1;
                v0.x = fmaf(p0.x + acc[i][j][0], osc, biasr[2 * j]);
                v0.y = fmaf(p0.y + acc[i][j][1], osc, biasr[2 * j + 1]);
                v1.x = fmaf(p1.x + acc[i][j][2], osc, biasr[2 * j]);
                v1.y = fmaf(p1.y + acc[i][j][3], osc, biasr[2 * j + 1]);
                *(float2*)&out[(size_t)m * DOUT + n]       = v0;
                *(float2*)&out[(size_t)(m + 8) * DOUT + n] = v1;
            }
        }
    }
}

// ============================================================================
// kernel_launch: 3 launches (amax, quant+flagreset, gemm split-K)
// ============================================================================
extern "C" void kernel_launch(void* const* d_in, const int* in_sizes, int n_in,
                              void* d_out, int out_size) {
    const float* x    = (const float*)d_in[0];   // [4,2048,2048]
    const float* w    = (const float*)d_in[1];   // [2048,2048]
    const float* bias = (const float*)d_in[2];   // [2048]
    float* out = (float*)d_out;

    static int smem_set = 0;
    if (!smem_set) {
        cudaFuncSetAttribute(gemm_kernel,
                             cudaFuncAttributeMaxDynamicSharedMemorySize,
                             GEMM_SMEM_BYTES);
        smem_set = 1;
    }

    amax_kernel<<<AMAX_XBLK + AMAX_WBLK, 256>>>((const float4*)x,
                                                (const float4*)w);
    quant_kernel<<<QUANT_XBLK + QUANT_WBLK, 256>>>((const float4*)x,
                                                   (const float4*)w);

    dim3 grid(DOUT / BN, M_TOTAL / BM, 2);  // (16, 64, 2) = 2048 CTAs
    gemm_kernel<<<grid, 256, GEMM_SMEM_BYTES>>>(out, bias);
}

// round 11
// speedup vs baseline: 1.1131x; 1.1131x over previous
#include <cuda_runtime.h>
#include <cuda_fp16.h>
#include <cstdint>

// ============================================================================
// Problem constants
// ============================================================================
#define M_TOTAL 8192   // B*S = 4*2048
#define DIN     2048
#define DOUT    2048
#define QDIV    358.4f // 448 * 0.8

// GEMM tiling (f16 carrier): 128x128 CTA tile, BK=64, 3 stages, 256 threads,
// 2 CTAs/SM. Hybrid split-K: first FULL tiles run full K (integer waves for
// both 296 and 304 slots); the last 136 tiles are split into K-halves that
// all fit in one final wave (makespan 3.5T instead of 4T).
#define BM 128
#define BN 128
#define BK 64
#define NIT_FULL (DIN / BK)      // 32
#define NIT_HALF (DIN / BK / 2)  // 16
#define STAGES 3
#define NTILES 1024
#define FULL   888
#define NSPLIT (NTILES - FULL)   // 136
#define NCTA   (FULL + 2 * NSPLIT)  // 1160

#define AMAX_XBLK 1024
#define AMAX_WBLK 512
#define QUANT_XBLK 4096
#define QUANT_WBLK 1024

// ============================================================================
// Device-global scratch (allocation-free requirement)
// ============================================================================
__device__ float g_px[AMAX_XBLK];   // per-block |x| maxes (plain stores)
__device__ float g_pw[AMAX_WBLK];   // per-block |w| maxes
__device__ float g_osc;             // sx*sw, published by quant block 0
__device__ unsigned g_flag[NSPLIT]; // split-K producer-done flags
__device__ __align__(128) float g_part[(size_t)NSPLIT * BM * BN];  // 8.9 MB
// fp8-rounded values stored as f16 (exact: e4m3 subset of f16)
__device__ __align__(128) __half g_qx[(size_t)M_TOTAL * DIN];   // 32 MB
__device__ __align__(128) __half g_qw[(size_t)DOUT * DIN];      //  8 MB

// ============================================================================
// Helpers
// ============================================================================
__device__ __forceinline__ uint32_t smem_to_u32(const void* p) {
    uint32_t a;
    asm("{ .reg .u64 t; cvta.to.shared.u64 t, %1; cvt.u32.u64 %0, t; }"
        : "=r"(a) : "l"(p));
    return a;
}

// fp32x2 -> packed e4m3x2 (RN, satfinite). low byte = lo, high byte = hi.
__device__ __forceinline__ uint16_t cvt_e4m3x2(float hi, float lo) {
    uint16_t r;
    asm("cvt.rn.satfinite.e4m3x2.f32 %0, %1, %2;" : "=h"(r) : "f"(hi), "f"(lo));
    return r;
}

// packed e4m3x2 -> f16x2 (exact)
__device__ __forceinline__ uint32_t cvt_f16x2_from_e4m3x2(uint16_t e) {
    uint32_t r;
    asm("cvt.rn.f16x2.e4m3x2 %0, %1;" : "=r"(r) : "h"(e));
    return r;
}

#define CP_ASYNC_16(dst, src) \
    asm volatile("cp.async.cg.shared.global [%0], [%1], 16;" \
                 :: "r"(dst), "l"(src))
#define CP_ASYNC_COMMIT() asm volatile("cp.async.commit_group;")
#define CP_ASYNC_WAIT_1() asm volatile("cp.async.wait_group 1;")

#define LDSM_X4(r, addr) \
    asm volatile("ldmatrix.sync.aligned.m8n8.x4.shared.b16 {%0,%1,%2,%3}, [%4];" \
        : "=r"((r)[0]), "=r"((r)[1]), "=r"((r)[2]), "=r"((r)[3]) : "r"(addr))

__device__ __forceinline__ void mma16816(float* d, const uint32_t* a,
                                         const uint32_t* b) {
    asm volatile(
        "mma.sync.aligned.m16n8k16.row.col.f32.f16.f16.f32 "
        "{%0,%1,%2,%3}, {%4,%5,%6,%7}, {%8,%9}, {%0,%1,%2,%3};"
        : "+f"(d[0]), "+f"(d[1]), "+f"(d[2]), "+f"(d[3])
        : "r"(a[0]), "r"(a[1]), "r"(a[2]), "r"(a[3]), "r"(b[0]), "r"(b[1]));
}

// SW128 swizzle for 128-byte rows (byte offsets)
__device__ __forceinline__ uint32_t swz(uint32_t off) {
    return off ^ ((off >> 3) & 0x70);
}

// div via reciprocal + one FMA residual refinement (== IEEE div for all but
// ~2^-40 of inputs; 3-mantissa-bit e4m3 RNE absorbs the rest)
__device__ __forceinline__ float div_cr(float x, float s, float inv) {
    float y = x * inv;
    float e = fmaf(-s, y, x);
    return fmaf(e, inv, y);
}

__device__ __forceinline__ float max4(float4 v) {
    return fmaxf(fmaxf(fabsf(v.x), fabsf(v.y)),
                 fmaxf(fabsf(v.z), fabsf(v.w)));
}

// block-level max reduction (256 threads), result valid in thread 0
__device__ __forceinline__ float block_max_256(float m, float* sred) {
    #pragma unroll
    for (int o = 16; o; o >>= 1)
        m = fmaxf(m, __shfl_xor_sync(0xFFFFFFFFu, m, o));
    if ((threadIdx.x & 31) == 0) sred[threadIdx.x >> 5] = m;
    __syncthreads();
    if (threadIdx.x < 8) {
        m = sred[threadIdx.x];
        #pragma unroll
        for (int o = 4; o; o >>= 1)
            m = fmaxf(m, __shfl_xor_sync(0xFFu, m, o));
    }
    return m;
}

// ============================================================================
// Kernel 1: fused amax over x (blocks [0,1024)) and w (blocks [1024,1536)).
// ============================================================================
__global__ void amax_kernel(const float4* __restrict__ x,
                            const float4* __restrict__ w) {
    __shared__ float sred[8];
    const bool is_w = blockIdx.x >= AMAX_XBLK;
    const float4* p = is_w ? w : x;
    const int n4 = is_w ? (DOUT * DIN / 4) : (M_TOTAL * DIN / 4);
    const int nblk = is_w ? AMAX_WBLK : AMAX_XBLK;
    const int b0 = is_w ? AMAX_XBLK : 0;
    const int bid = blockIdx.x - b0;
    const int stride = nblk * 256 * 4;
    float m0 = 0.0f, m1 = 0.0f, m2 = 0.0f, m3 = 0.0f;
    for (int i = bid * 256 * 4 + threadIdx.x; i < n4; i += stride) {
        float4 v0 = p[i];
        float4 v1 = p[i + 256];
        float4 v2 = p[i + 512];
        float4 v3 = p[i + 768];
        m0 = fmaxf(m0, max4(v0));
        m1 = fmaxf(m1, max4(v1));
        m2 = fmaxf(m2, max4(v2));
        m3 = fmaxf(m3, max4(v3));
    }
    float m = fmaxf(fmaxf(m0, m1), fmaxf(m2, m3));
    m = block_max_256(m, sred);
    if (threadIdx.x == 0) {
        if (is_w) g_pw[bid] = m;
        else      g_px[bid] = m;
    }
}

// ============================================================================
// Kernel 2: fused quantize x/w + split-K flag reset (block 0).
// Block 0 publishes g_osc.
// ============================================================================
__global__ void quant_kernel(const float4* __restrict__ x,
                             const float4* __restrict__ w) {
    __shared__ float sred[8];
    __shared__ float s_ax, s_aw;
    // reset split-K flags for the upcoming gemm (stream-ordered before it)
    if (blockIdx.x == 0 && threadIdx.x < NSPLIT)
        g_flag[threadIdx.x] = 0u;
    {
        float mx = 0.0f, mw = 0.0f;
        #pragma unroll
        for (int q = 0; q < 4; ++q)
            mx = fmaxf(mx, g_px[threadIdx.x + q * 256]);
        #pragma unroll
        for (int q = 0; q < 2; ++q)
            mw = fmaxf(mw, g_pw[threadIdx.x + q * 256]);
        float rx = block_max_256(mx, sred);
        if (threadIdx.x == 0) s_ax = rx;
        __syncthreads();
        float rw = block_max_256(mw, sred);
        if (threadIdx.x == 0) s_aw = rw;
        __syncthreads();
    }
    const float ax = s_ax, aw = s_aw;
    if (blockIdx.x == 0 && threadIdx.x == 0)
        g_osc = (ax / QDIV) * (fmaxf(ax, aw) / QDIV);

    const bool is_w = blockIdx.x >= QUANT_XBLK;
    const float s   = is_w ? (fmaxf(ax, aw) / QDIV) : (ax / QDIV);
    const float inv = 1.0f / s;
    const float4* p = is_w ? w : x;
    uint4* q = (uint4*)(is_w ? (void*)g_qw : (void*)g_qx);
    const int n8 = (is_w ? (DOUT * DIN) : (M_TOTAL * DIN)) / 8;
    const int nblk = is_w ? QUANT_WBLK : QUANT_XBLK;
    const int b0 = is_w ? QUANT_XBLK : 0;
    for (int i = (blockIdx.x - b0) * 256 + threadIdx.x; i < n8;
         i += nblk * 256) {
        float4 v0 = p[2 * i];
        float4 v1 = p[2 * i + 1];
        uint4 o;
        o.x = cvt_f16x2_from_e4m3x2(cvt_e4m3x2(div_cr(v0.y, s, inv),
                                               div_cr(v0.x, s, inv)));
        o.y = cvt_f16x2_from_e4m3x2(cvt_e4m3x2(div_cr(v0.w, s, inv),
                                               div_cr(v0.z, s, inv)));
        o.z = cvt_f16x2_from_e4m3x2(cvt_e4m3x2(div_cr(v1.y, s, inv),
                                               div_cr(v1.x, s, inv)));
        o.w = cvt_f16x2_from_e4m3x2(cvt_e4m3x2(div_cr(v1.w, s, inv),
                                               div_cr(v1.z, s, inv)));
        q[i] = o;
    }
}

// ============================================================================
// Kernel 3: f16 HMMA GEMM, hybrid split-K.
// bid <  888:        full tile, K = [0,2048)
// 888 <= bid < 1024: producer half of tile bid, K = [0,1024) -> partial+flag
// bid >= 1024:       consumer half of tile bid-136, K = [1024,2048) ->
//                    spin, combine, scale+bias, store.
// Producer bid < consumer bid -> dispatch order guarantees progress.
// ============================================================================
#define STAGE_BYTES 32768                 // A 16KB + B 16KB
#define GEMM_SMEM_BYTES (STAGES * STAGE_BYTES)   // 98304

__global__ __launch_bounds__(256, 2) void gemm_kernel(
    float* __restrict__ out, const float* __restrict__ bias)
{
    extern __shared__ char smem[];
    const uint32_t sb = smem_to_u32(smem);
    const int tid  = threadIdx.x;
    const int lane = tid & 31;
    const int warp = tid >> 5;
    const int wm = warp >> 2;       // 0..1
    const int wn = warp & 3;        // 0..3

    // ---- tile decode ----
    const int bid = blockIdx.x;
    int tile, nit, mode;            // mode: 0=full, 1=producer, 2=consumer
    size_t koff;
    if (bid < FULL)            { tile = bid;          nit = NIT_FULL; mode = 0; koff = 0; }
    else if (bid < FULL + NSPLIT) { tile = bid;       nit = NIT_HALF; mode = 1; koff = 0; }
    else                       { tile = bid - NSPLIT; nit = NIT_HALF; mode = 2; koff = DIN / 2; }
    const int mt = tile >> 4;       // 0..63
    const int nt = tile & 15;       // 0..15

    const __half* gA = g_qx + (size_t)mt * BM * DIN + koff;
    const __half* gB = g_qw + (size_t)nt * BN * DIN + koff;

    // ---- per-thread cp.async chunk map: 4 chunks A + 4 chunks B per stage ----
    uint32_t dstA[4], dstB[4];
    const char* srcA[4];
    const char* srcB[4];
    #pragma unroll
    for (int q = 0; q < 4; ++q) {
        int ch  = tid + q * 256;
        int row = ch >> 3;
        int cb  = (ch & 7) * 16;
        uint32_t sw = swz((uint32_t)(row * 128 + cb));
        dstA[q] = sw;
        dstB[q] = 16384u + sw;
        srcA[q] = (const char*)(gA + (size_t)row * DIN) + cb;
        srcB[q] = (const char*)(gB + (size_t)row * DIN) + cb;
    }

    // ---- prologue: fill STAGES-1 stages ----
    int li = 0;
    #pragma unroll
    for (int s = 0; s < STAGES - 1; ++s) {
        uint32_t st = sb + s * STAGE_BYTES;
        #pragma unroll
        for (int q = 0; q < 4; ++q) {
            CP_ASYNC_16(st + dstA[q], srcA[q] + li * (BK * 2));
            CP_ASYNC_16(st + dstB[q], srcB[q] + li * (BK * 2));
        }
        CP_ASYNC_COMMIT();
        ++li;
    }
    CP_ASYNC_WAIT_1();
    __syncthreads();

    // ---- ldmatrix per-lane address components ----
    const int rA = wm * 64 + (lane & 7) + ((lane >> 3) & 1) * 8;
    const uint32_t cA0 = ((lane >> 4) & 1) * 16;
    const uint32_t xrA = (uint32_t)((rA & 7) << 4);
    const int rB = wn * 32 + (lane & 7) + ((lane >> 4) & 1) * 8;
    const uint32_t cB0 = ((lane >> 3) & 1) * 16;
    const uint32_t xrB = (uint32_t)((rB & 7) << 4);

    float acc[4][4][4];
    #pragma unroll
    for (int i = 0; i < 4; ++i)
        #pragma unroll
        for (int j = 0; j < 4; ++j)
            #pragma unroll
            for (int r = 0; r < 4; ++r) acc[i][j][r] = 0.0f;

    // double-buffered fragments
    uint32_t afr[2][4][4];
    uint32_t bfr[2][2][4];

    // ---- main loop ----
    #pragma unroll 1
    for (int it = 0; it < nit; ++it) {
        const int cur = it % STAGES;
        const uint32_t stA = sb + cur * STAGE_BYTES;
        const uint32_t stB = stA + 16384;

        // k0 fragment preload FIRST (stage cur complete & synced); its LDSM
        // latency overlaps the cp.async issue below.
        #pragma unroll
        for (int i = 0; i < 4; ++i)
            LDSM_X4(afr[0][i], stA + (uint32_t)((rA + i * 16) * 128) + (cA0 ^ xrA));
        #pragma unroll
        for (int jj = 0; jj < 2; ++jj)
            LDSM_X4(bfr[0][jj], stB + (uint32_t)((rB + jj * 16) * 128) + (cB0 ^ xrB));

        if (li < nit) {
            const int nx = (it + STAGES - 1) % STAGES;
            uint32_t st = sb + nx * STAGE_BYTES;
            #pragma unroll
            for (int q = 0; q < 4; ++q) {
                CP_ASYNC_16(st + dstA[q], srcA[q] + li * (BK * 2));
                CP_ASYNC_16(st + dstB[q], srcB[q] + li * (BK * 2));
            }
            ++li;
        }
        CP_ASYNC_COMMIT();

        #pragma unroll
        for (int s = 0; s < 4; ++s) {
            const int cb = s & 1, nb = cb ^ 1;
            if (s < 3) {
                #pragma unroll
                for (int i = 0; i < 4; ++i)
                    LDSM_X4(afr[nb][i], stA + (uint32_t)((rA + i * 16) * 128)
                                            + ((cA0 + (s + 1) * 32) ^ xrA));
                #pragma unroll
                for (int jj = 0; jj < 2; ++jj)
                    LDSM_X4(bfr[nb][jj], stB + (uint32_t)((rB + jj * 16) * 128)
                                             + ((cB0 + (s + 1) * 32) ^ xrB));
            }
            #pragma unroll
            for (int i = 0; i < 4; ++i)
                #pragma unroll
                for (int j = 0; j < 4; ++j)
                    mma16816(acc[i][j], afr[cb][i], bfr[cb][j >> 1] + (j & 1) * 2);
        }

        CP_ASYNC_WAIT_1();
        __syncthreads();
    }

    const int ml = wm * 64 + (lane >> 2);      // local m within tile
    const int nl = wn * 32 + (lane & 3) * 2;   // local n within tile

    if (mode == 1) {
        // ---- producer: raw partials to L2-resident scratch, then flag ----
        float* part = g_part + (size_t)(tile - FULL) * (BM * BN);
        #pragma unroll
        for (int i = 0; i < 4; ++i) {
            #pragma unroll
            for (int j = 0; j < 4; ++j) {
                const int m = ml + i * 16;
                const int n = nl + j * 8;
                float2 v0, v1;
                v0.x = acc[i][j][0]; v0.y = acc[i][j][1];
                v1.x = acc[i][j][2]; v1.y = acc[i][j][3];
                *(float2*)&part[(size_t)m * BN + n]       = v0;
                *(float2*)&part[(size_t)(m + 8) * BN + n] = v1;
            }
        }
        __threadfence();
        __syncthreads();
        if (tid == 0) atomicExch(&g_flag[tile - FULL], 1u);
        return;
    }

    const float osc = g_osc;
    const int m0 = mt * BM + ml;
    const int n0 = nt * BN + nl;

    if (mode == 2) {
        // ---- consumer: wait for co-resident producer, combine ----
        if (tid == 0) {
            while (atomicAdd(&g_flag[tile - FULL], 0u) == 0u) __nanosleep(64);
        }
        __syncthreads();
        const float* part = g_part + (size_t)(tile - FULL) * (BM * BN);
        #pragma unroll
        for (int i = 0; i < 4; ++i) {
            #pragma unroll
            for (int j = 0; j < 4; ++j) {
                const int m = m0 + i * 16;
                const int n = n0 + j * 8;
                const int lm = ml + i * 16;
                const int ln = nl + j * 8;
                const float b0 = __ldg(&bias[n]);
                const float b1 = __ldg(&bias[n + 1]);
                float2 p0 = __ldcg((const float2*)&part[(size_t)lm * BN + ln]);
                float2 p1 = __ldcg((const float2*)&part[(size_t)(lm + 8) * BN + ln]);
                float2 v0, v1;
                v0.x = fmaf(p0.x + acc[i][j][0], osc, b0);
                v0.y = fmaf(p0.y + acc[i][j][1], osc, b1);
                v1.x = fmaf(p1.x + acc[i][j][2], osc, b0);
                v1.y = fmaf(p1.y + acc[i][j][3], osc, b1);
                *(float2*)&out[(size_t)m * DOUT + n]       = v0;
                *(float2*)&out[(size_t)(m + 8) * DOUT + n] = v1;
            }
        }
        return;
    }

    // ---- full tile: scale + bias, store ----
    #pragma unroll
    for (int i = 0; i < 4; ++i) {
        #pragma unroll
        for (int j = 0; j < 4; ++j) {
            const int m = m0 + i * 16;
            const int n = n0 + j * 8;
            const float b0 = __ldg(&bias[n]);
            const float b1 = __ldg(&bias[n + 1]);
            float2 v0, v1;
            v0.x = fmaf(acc[i][j][0], osc, b0);
            v0.y = fmaf(acc[i][j][1], osc, b1);
            v1.x = fmaf(acc[i][j][2], osc, b0);
            v1.y = fmaf(acc[i][j][3], osc, b1);
            *(float2*)&out[(size_t)m * DOUT + n]       = v0;
            *(float2*)&out[(size_t)(m + 8) * DOUT + n] = v1;
        }
    }
}

// ============================================================================
// kernel_launch: 3 launches (amax, quant+flagreset, gemm hybrid split-K)
// ============================================================================
extern "C" void kernel_launch(void* const* d_in, const int* in_sizes, int n_in,
                              void* d_out, int out_size) {
    const float* x    = (const float*)d_in[0];   // [4,2048,2048]
    const float* w    = (const float*)d_in[1];   // [2048,2048]
    const float* bias = (const float*)d_in[2];   // [2048]
    float* out = (float*)d_out;

    static int smem_set = 0;
    if (!smem_set) {
        cudaFuncSetAttribute(gemm_kernel,
                             cudaFuncAttributeMaxDynamicSharedMemorySize,
                             GEMM_SMEM_BYTES);
        smem_set = 1;
    }

    amax_kernel<<<AMAX_XBLK + AMAX_WBLK, 256>>>((const float4*)x,
                                                (const float4*)w);
    quant_kernel<<<QUANT_XBLK + QUANT_WBLK, 256>>>((const float4*)x,
                                                   (const float4*)w);

    gemm_kernel<<<NCTA, 256, GEMM_SMEM_BYTES>>>(out, bias);
}